// round 13
// baseline (speedup 1.0000x reference)
#include <cuda_runtime.h>
#include <stdint.h>

// x: [B=16, C=128, H=224, W=224] fp32, perm: [B=16, 16] int32
// G=4, block = 56x56 per image plane. Output block o <- input block inv_perm[o].
//
// Bulk-store variant: each CTA assembles its 28 KB contiguous output slab
// (32 rows x 896 B) in SMEM, then emits it as ONE cp.async.bulk shared->global
// transfer. Rationale: all SM-side levers are exhausted at ~6.65 TB/s DRAM;
// the residual vs spec is read<->write turnaround, and multi-KB TMA write
// bursts give the DRAM controller longer sequential write runs than 512 B
// warp STG wavefronts.
//
// Read side unchanged from the proven R3 config: 8 front-batched .cs loads
// per thread, perm lookup amortized (56 % 8 == 0), grid (7, C, B),
// blockDim (56, 4).

#define G2 16
#define SLAB_F4 (32 * 56)            // 1792 float4 = 28672 B per CTA slab

__global__ __launch_bounds__(224) void block_shuffle_kernel(
    const float4* __restrict__ x,
    const int*    __restrict__ perm,
    float4*       __restrict__ out)
{
    __shared__ int    s_inv[G2];
    __shared__ __align__(128) float4 s_tile[SLAB_F4];   // 28 KB staging

    const int b = blockIdx.z;
    const int c = blockIdx.y;

    const int tid = threadIdx.y * 56 + threadIdx.x;
    if (tid < G2) {
        // perm[b][k] = o  (output slot of input block k)  ->  inv[o] = k
        const int o = perm[b * G2 + tid];
        s_inv[o] = tid;
    }
    __syncthreads();

    const int w4 = threadIdx.x;                              // 0..55
    const int r0 = threadIdx.y * 8;                          // local row 0,8,16,24
    const int h0 = blockIdx.x * 32 + r0;                     // global output row

    const int j = w4 / 14;          // output block col (const-div -> mul)
    const int i = h0 / 56;          // output block row (constant over 8 rows)
    const int k = s_inv[i * 4 + j];
    const int si = k >> 2;
    const int sj = k & 3;

    const int sh0 = si * 56 + (h0 - i * 56);
    const int sw4 = sj * 14 + (w4 - j * 14);

    const int plane = (b * 128 + c) * 224;                   // row base (in rows)
    const float4* __restrict__ src = x + ((long)(plane + sh0)) * 56 + sw4;

    // 8 front-batched independent streaming loads
    float4 v0 = __ldcs(src);
    float4 v1 = __ldcs(src +  56);
    float4 v2 = __ldcs(src + 112);
    float4 v3 = __ldcs(src + 168);
    float4 v4 = __ldcs(src + 224);
    float4 v5 = __ldcs(src + 280);
    float4 v6 = __ldcs(src + 336);
    float4 v7 = __ldcs(src + 392);

    // stage into SMEM at output layout (warp writes 32 consecutive float4s
    // per row -> conflict-free)
    float4* st = s_tile + r0 * 56 + w4;
    st[  0] = v0;
    st[ 56] = v1;
    st[112] = v2;
    st[168] = v3;
    st[224] = v4;
    st[280] = v5;
    st[336] = v6;
    st[392] = v7;

    __syncthreads();

    if (tid == 0) {
        // make generic-proxy SMEM writes visible to the async (TMA) proxy
        asm volatile("fence.proxy.async.shared::cta;" ::: "memory");

        uint32_t saddr;
        asm("{ .reg .u64 t; cvta.to.shared.u64 t, %1; cvt.u32.u64 %0, t; }"
            : "=r"(saddr) : "l"(s_tile));

        float4* dst = out + ((long)(plane + blockIdx.x * 32)) * 56;

        // one 28 KB contiguous bulk store
        asm volatile(
            "cp.async.bulk.global.shared::cta.bulk_group [%0], [%1], %2;"
            :: "l"(dst), "r"(saddr), "r"((int)(SLAB_F4 * 16)) : "memory");
        asm volatile("cp.async.bulk.commit_group;" ::: "memory");
        // must complete before CTA exit (SMEM is the source)
        asm volatile("cp.async.bulk.wait_group.read 0;" ::: "memory");
    }
}

extern "C" void kernel_launch(void* const* d_in, const int* in_sizes, int n_in,
                              void* d_out, int out_size)
{
    const float4* x    = (const float4*)d_in[0];
    const int*    perm = (const int*)d_in[1];
    float4*       out  = (float4*)d_out;

    dim3 grid(224 / 32, 128, 16);   // (7, C, B)
    dim3 block(56, 4);
    block_shuffle_kernel<<<grid, block>>>(x, perm, out);
}

// round 14
// speedup vs baseline: 1.3681x; 1.3681x over previous
#include <cuda_runtime.h>
#include <stdint.h>

// x: [B=16, C=128, H=224, W=224] fp32, perm: [B=16, 16] int32
// G=4, block = 56x56 per image plane. Output block o <- input block inv_perm[o].
//
// FINAL kernel — at the HBM floor for this bidirectional permutation copy:
// 822 MB in ~116 us kernel time = 7.1 TB/s effective (89% of 8 TB/s spec).
// Exhaustively shown invariant to: MLP (1/4/8), access width (128/256-bit),
// occupancy (37-84%), L2 policy (evict-normal stores, 256B promotion,
// evict_last pinning), CTA persistence, and TMA bulk stores (last two
// regressed). Residual vs spec = DRAM read<->write turnaround.
//
// Geometry: grid = (H/32, C, B) = (7, 128, 16), blockDim = (56, 4).
//   threadIdx.x = w4 (float4 column, 0..55)
//   each (blockIdx.x, threadIdx.y) handles an 8-row group; 56 % 8 == 0 keeps
//   all 8 rows in one output block row -> perm lookup + index math amortize
//   8x, 8 front-batched independent loads (MLP=8).
// Cache policy: evict-first (.cs) on BOTH streams.

#define G2 16

__global__ __launch_bounds__(224) void block_shuffle_kernel(
    const float4* __restrict__ x,
    const int*    __restrict__ perm,
    float4*       __restrict__ out)
{
    __shared__ int s_inv[G2];

    const int b = blockIdx.z;
    const int c = blockIdx.y;

    const int tid = threadIdx.y * 56 + threadIdx.x;
    if (tid < G2) {
        // perm[b][k] = o  (output slot of input block k)  ->  inv[o] = k
        const int o = perm[b * G2 + tid];
        s_inv[o] = tid;
    }
    __syncthreads();

    const int w4 = threadIdx.x;                              // 0..55
    const int h0 = (blockIdx.x * 4 + threadIdx.y) * 8;       // 0,8,...,216

    const int j = w4 / 14;          // output block col (const-div -> mul)
    const int i = h0 / 56;          // output block row (constant over 8 rows)
    const int k = s_inv[i * 4 + j];
    const int si = k >> 2;
    const int sj = k & 3;

    const int sh0 = si * 56 + (h0 - i * 56);
    const int sw4 = sj * 14 + (w4 - j * 14);

    const int plane = (b * 128 + c) * 224;                   // row base (in rows)
    const float4* __restrict__ src = x   + ((long)(plane + sh0)) * 56 + sw4;
    float4*       __restrict__ dst = out + ((long)(plane + h0 )) * 56 + w4;

    // 8 independent streaming loads (front-batched), then 8 streaming stores
    float4 v0 = __ldcs(src);
    float4 v1 = __ldcs(src +  56);
    float4 v2 = __ldcs(src + 112);
    float4 v3 = __ldcs(src + 168);
    float4 v4 = __ldcs(src + 224);
    float4 v5 = __ldcs(src + 280);
    float4 v6 = __ldcs(src + 336);
    float4 v7 = __ldcs(src + 392);

    __stcs(dst,       v0);
    __stcs(dst +  56, v1);
    __stcs(dst + 112, v2);
    __stcs(dst + 168, v3);
    __stcs(dst + 224, v4);
    __stcs(dst + 280, v5);
    __stcs(dst + 336, v6);
    __stcs(dst + 392, v7);
}

extern "C" void kernel_launch(void* const* d_in, const int* in_sizes, int n_in,
                              void* d_out, int out_size)
{
    const float4* x    = (const float4*)d_in[0];
    const int*    perm = (const int*)d_in[1];
    float4*       out  = (float4*)d_out;

    dim3 grid(224 / 32, 128, 16);   // (7, C, B)
    dim3 block(56, 4);
    block_shuffle_kernel<<<grid, block>>>(x, perm, out);
}

// round 15
// speedup vs baseline: 1.3717x; 1.0026x over previous
#include <cuda_runtime.h>
#include <stdint.h>

// x: [B=16, C=128, H=224, W=224] fp32, perm: [B=16, 16] int32
// G=4, block = 56x56 per image plane. torch semantics: out block perm[k] = in block k.
//
// SCATTER orientation (mirror of the gather floor-config): reads are fully
// sequential per thread/CTA (long DRAM read bursts, zero line-straddle
// waste); the 224B-segmented side moves to the write stream, where L2
// write-merging of adjacent segments from concurrent CTAs is deterministic
// (lines fill before writeback) rather than timing-dependent read dedup.
//
// Geometry: grid = (H/32, C, B) = (7, 128, 16), blockDim = (56, 4).
//   threadIdx.x = w4 (input float4 column, 0..55)
//   each (blockIdx.x, threadIdx.y) handles an 8-row INPUT group; 56 % 8 == 0
//   keeps all 8 rows in one input block row -> perm lookup + index math
//   amortize 8x, 8 front-batched independent loads (MLP=8).
// Cache policy: evict-first (.cs) on BOTH streams (validated).

#define G2 16

__global__ __launch_bounds__(224) void block_shuffle_kernel(
    const float4* __restrict__ x,
    const int*    __restrict__ perm,
    float4*       __restrict__ out)
{
    __shared__ int s_perm[G2];

    const int b = blockIdx.z;
    const int c = blockIdx.y;

    const int tid = threadIdx.y * 56 + threadIdx.x;
    if (tid < G2) {
        // out block perm[b][k] <- in block k  (scatter; no inversion needed)
        s_perm[tid] = perm[b * G2 + tid];
    }
    __syncthreads();

    const int w4 = threadIdx.x;                              // 0..55 (input col)
    const int h0 = (blockIdx.x * 4 + threadIdx.y) * 8;       // input row 0,8,...,216

    const int j = w4 / 14;          // input block col (const-div -> mul)
    const int i = h0 / 56;          // input block row (constant over 8 rows)
    const int o  = s_perm[i * 4 + j];                        // destination block
    const int di = o >> 2;
    const int dj = o & 3;

    const int dh0 = di * 56 + (h0 - i * 56);
    const int dw4 = dj * 14 + (w4 - j * 14);

    const int plane = (b * 128 + c) * 224;                   // row base (in rows)
    const float4* __restrict__ src = x   + ((long)(plane + h0 )) * 56 + w4;
    float4*       __restrict__ dst = out + ((long)(plane + dh0)) * 56 + dw4;

    // 8 independent sequential streaming loads (front-batched), then 8
    // block-permuted streaming stores
    float4 v0 = __ldcs(src);
    float4 v1 = __ldcs(src +  56);
    float4 v2 = __ldcs(src + 112);
    float4 v3 = __ldcs(src + 168);
    float4 v4 = __ldcs(src + 224);
    float4 v5 = __ldcs(src + 280);
    float4 v6 = __ldcs(src + 336);
    float4 v7 = __ldcs(src + 392);

    __stcs(dst,       v0);
    __stcs(dst +  56, v1);
    __stcs(dst + 112, v2);
    __stcs(dst + 168, v3);
    __stcs(dst + 224, v4);
    __stcs(dst + 280, v5);
    __stcs(dst + 336, v6);
    __stcs(dst + 392, v7);
}

extern "C" void kernel_launch(void* const* d_in, const int* in_sizes, int n_in,
                              void* d_out, int out_size)
{
    const float4* x    = (const float4*)d_in[0];
    const int*    perm = (const int*)d_in[1];
    float4*       out  = (float4*)d_out;

    dim3 grid(224 / 32, 128, 16);   // (7, C, B)
    dim3 block(56, 4);
    block_shuffle_kernel<<<grid, block>>>(x, perm, out);
}